// round 1
// baseline (speedup 1.0000x reference)
#include <cuda_runtime.h>

#define NB   8192
#define NOPT 16
#define DIM  768
#define F4_PER_ROW (DIM / 4)   // 192
#define MARGIN 0.3f

// Scratch: per-sample partial results (deterministic two-pass reduction).
__device__ float g_loss[NB];
__device__ int   g_cnt[NB];

// pair index for (i<=j) in triangular enumeration; folds to a constant under unroll
__device__ __forceinline__ constexpr int pidx(int i, int j) {
    return i * NOPT - (i * (i - 1)) / 2 + (j - i);
}

template <int LO, int HI>
__device__ __forceinline__ void accum_pairs(float (&acc)[HI - LO], const float4 (&x)[NOPT]) {
#pragma unroll
    for (int i = 0; i < NOPT; ++i) {
#pragma unroll
        for (int j = i; j < NOPT; ++j) {
            const int p = pidx(i, j);
            if (p >= LO && p < HI) {
                float a = acc[p - LO];
                a = fmaf(x[i].x, x[j].x, a);
                a = fmaf(x[i].y, x[j].y, a);
                a = fmaf(x[i].z, x[j].z, a);
                a = fmaf(x[i].w, x[j].w, a);
                acc[p - LO] = a;
            }
        }
    }
}

template <int LO, int HI>
__device__ __forceinline__ void reduce_store(float (&acc)[HI - LO], float* G, int lane) {
#pragma unroll
    for (int i = 0; i < NOPT; ++i) {
#pragma unroll
        for (int j = i; j < NOPT; ++j) {
            const int p = pidx(i, j);
            if (p >= LO && p < HI) {
                float v = acc[p - LO];
                v += __shfl_xor_sync(0xFFFFFFFFu, v, 16);
                v += __shfl_xor_sync(0xFFFFFFFFu, v, 8);
                v += __shfl_xor_sync(0xFFFFFFFFu, v, 4);
                v += __shfl_xor_sync(0xFFFFFFFFu, v, 2);
                v += __shfl_xor_sync(0xFFFFFFFFu, v, 1);
                if (lane == 0) {
                    G[i * NOPT + j] = v;
                    G[j * NOPT + i] = v;
                }
            }
        }
    }
}

__global__ void __launch_bounds__(64)
cf_main(const float* __restrict__ emb, const long long* __restrict__ labels) {
    const int b    = blockIdx.x;
    const int tid  = threadIdx.x;
    const int warp = tid >> 5;
    const int lane = tid & 31;

    __shared__ float G[NOPT * NOPT];
    __shared__ float invn[NOPT];
    __shared__ int   lab[NOPT];

    if (tid < NOPT) lab[tid] = (int)labels[(size_t)b * NOPT + tid];

    const float4* base = reinterpret_cast<const float4*>(emb + (size_t)b * NOPT * DIM);

    float4 x[NOPT];
    if (warp == 0) {
        float acc[68] = {};
        for (int k = 0; k < 6; ++k) {
            const float4* p0 = base + lane + 32 * k;
#pragma unroll
            for (int n = 0; n < NOPT; ++n) x[n] = p0[n * F4_PER_ROW];
            accum_pairs<0, 68>(acc, x);
        }
        reduce_store<0, 68>(acc, G, lane);
    } else {
        float acc[68] = {};
        for (int k = 0; k < 6; ++k) {
            const float4* p0 = base + lane + 32 * k;
#pragma unroll
            for (int n = 0; n < NOPT; ++n) x[n] = p0[n * F4_PER_ROW];
            accum_pairs<68, 136>(acc, x);
        }
        reduce_store<68, 136>(acc, G, lane);
    }
    __syncthreads();

    // Inverse norms (diagonal of G). Data is N(0,1): norms ~27, eps path moot but guarded.
    if (tid < NOPT) invn[tid] = rsqrtf(fmaxf(G[tid * NOPT + tid], 1e-24f));
    __syncthreads();

    if (tid < NOPT) {
        const int  n     = tid;
        const bool isPos = (lab[n] == 1);
        const bool isNeg = (lab[n] == 0);
        const unsigned posm = __ballot_sync(0x0000FFFFu, isPos) & 0xFFFFu;
        const unsigned negm = __ballot_sync(0x0000FFFFu, isNeg) & 0xFFFFu;
        const bool valid = (posm != 0u) && (negm != 0u);

        const float in_ = invn[n];
        float mx = -1e9f;   // NEG_INF sentinel, matches reference
#pragma unroll
        for (int m = 0; m < NOPT; ++m) {
            if (lab[m] == 0) mx = fmaxf(mx, G[n * NOPT + m] * in_ * invn[m]);
        }
        const float trip = fmaxf(mx + MARGIN, 0.0f);
        float contrib = (isPos && valid) ? trip : 0.0f;

        contrib += __shfl_xor_sync(0x0000FFFFu, contrib, 8);
        contrib += __shfl_xor_sync(0x0000FFFFu, contrib, 4);
        contrib += __shfl_xor_sync(0x0000FFFFu, contrib, 2);
        contrib += __shfl_xor_sync(0x0000FFFFu, contrib, 1);

        if (tid == 0) {
            g_loss[b] = contrib;
            g_cnt[b]  = valid ? __popc(posm) : 0;
        }
    }
}

__global__ void cf_final(float* __restrict__ out) {
    __shared__ float ssum[256];
    __shared__ int   scnt[256];
    const int tid = threadIdx.x;
    float s = 0.0f;
    int   c = 0;
    for (int i = tid; i < NB; i += 256) { s += g_loss[i]; c += g_cnt[i]; }
    ssum[tid] = s;
    scnt[tid] = c;
    __syncthreads();
#pragma unroll
    for (int off = 128; off > 0; off >>= 1) {
        if (tid < off) { ssum[tid] += ssum[tid + off]; scnt[tid] += scnt[tid + off]; }
        __syncthreads();
    }
    if (tid == 0) out[0] = ssum[0] / (float)(scnt[0] > 0 ? scnt[0] : 1);
}

extern "C" void kernel_launch(void* const* d_in, const int* in_sizes, int n_in,
                              void* d_out, int out_size) {
    const float*     emb    = (const float*)d_in[0];
    const long long* labels = (const long long*)d_in[1];
    float*           out    = (float*)d_out;

    cf_main<<<NB, 64>>>(emb, labels);
    cf_final<<<1, 256>>>(out);
}